// round 10
// baseline (speedup 1.0000x reference)
#include <cuda_runtime.h>
#include <cstdint>

// Problem constants (fixed shapes for this problem instance)
#define Lc     2048
#define Bc     2
#define Hc     32
#define Pc     64
#define Nc     128
#define DPROJ  4384      // 2*d_inner + 2*dstate + nheads
#define DCONVC 2304      // d_inner + 2*dstate
#define DINNER 2048

// ---------------- scratch (static device globals; no runtime alloc) ---------
// x / gate planes: [q8 = ((b*H + h)*8 + peighth)][t][8]
__device__ __align__(16) float g_x [(size_t)Bc * Hc * 8 * Lc * 8];    // 33.5 MB
__device__ __align__(16) float g_g [(size_t)Bc * Hc * 8 * Lc * 8];    // 33.5 MB
__device__ __align__(16) float g_B [(size_t)Bc * Lc * Nc];            // 2 MB
__device__ __align__(16) float g_C [(size_t)Bc * Lc * Nc];            // 2 MB
__device__ __align__(16) float g_dtA[(size_t)Bc * Hc * Lc * 2];       // 1 MB

// ---------------- packed f32x2 helpers --------------------------------------
__device__ __forceinline__ uint64_t pk2(float lo, float hi) {
    uint64_t r;
    asm("mov.b64 %0, {%1,%2};" : "=l"(r) : "f"(lo), "f"(hi));
    return r;
}
__device__ __forceinline__ void unpk2(uint64_t v, float& lo, float& hi) {
    asm("mov.b64 {%0,%1}, %2;" : "=f"(lo), "=f"(hi) : "l"(v));
}
__device__ __forceinline__ uint64_t f2fma(uint64_t a, uint64_t b, uint64_t c) {
    uint64_t d;
    asm("fma.rn.f32x2 %0, %1, %2, %3;" : "=l"(d) : "l"(a), "l"(b), "l"(c));
    return d;
}
__device__ __forceinline__ uint64_t f2mul(uint64_t a, uint64_t b) {
    uint64_t d;
    asm("mul.rn.f32x2 %0, %1, %2;" : "=l"(d) : "l"(a), "l"(b));
    return d;
}
__device__ __forceinline__ void cpa16(void* sm, const void* gm) {
    unsigned sa = (unsigned)__cvta_generic_to_shared(sm);
    asm volatile("cp.async.cg.shared.global [%0], [%1], 16;" :: "r"(sa), "l"(gm));
}
__device__ __forceinline__ float fast_silu(float v) {
    return v * (1.f / (1.f + __expf(-v)));
}

// ---------------- pre-pass: conv + SiLU + dt/dA + gate, routed to scratch ---
__global__ void prepass_kernel(const float* __restrict__ zx,
                               const float* __restrict__ cw,
                               const float* __restrict__ cb,
                               const float* __restrict__ dt_bias,
                               const float* __restrict__ a_log,
                               const float* __restrict__ dt_scale) {
    int bt  = blockIdx.x;            // b*L + t
    int b   = bt >> 11;
    int t   = bt & (Lc - 1);
    int idx = blockIdx.y * 256 + threadIdx.x;   // "work channel"
    if (idx >= DPROJ) return;

    const float* row = zx + (size_t)bt * DPROJ;

    if (idx < DINNER) {
        float z = row[idx];
        int h = idx >> 6, p = idx & 63;
        g_g[(((((size_t)b * Hc + h) * 8 + (p >> 3)) * Lc) + t) * 8 + (p & 7)] = fast_silu(z);
    } else if (idx < DINNER + DCONVC) {
        int cc = idx - DINNER;
        float acc = cb[cc];
        const float* w = cw + cc * 4;
        #pragma unroll
        for (int i = 0; i < 4; ++i) {
            int l2 = t - 3 + i;
            if (l2 >= 0) acc += w[i] * zx[((size_t)(b * Lc + l2)) * DPROJ + idx];
        }
        float v = fast_silu(acc);
        if (cc < DINNER) {
            int h = cc >> 6, p = cc & 63;
            g_x[(((((size_t)b * Hc + h) * 8 + (p >> 3)) * Lc) + t) * 8 + (p & 7)] = v;
        } else if (cc < DINNER + Nc) {
            g_B[((size_t)(b * Lc + t)) * Nc + (cc - DINNER)] = v;
        } else {
            g_C[((size_t)(b * Lc + t)) * Nc + (cc - DINNER - Nc)] = v;
        }
    } else {
        int h = idx - (DINNER + DCONVC);
        float v  = row[DPROJ - Hc + h] * dt_scale[h] + dt_bias[h];
        float dt = (v > 20.f) ? v : log1pf(expf(v));
        dt = fminf(fmaxf(dt, 0.f), 100.f);
        float A  = -expf(a_log[h]);
        float dA = expf(dt * A);
        size_t o = ((size_t)(b * Hc + h) * Lc + t) * 2;
        g_dtA[o]     = dt;
        g_dtA[o + 1] = dA;
    }
}

// ---------------- scan kernel -----------------------------------------------
// grid = 512 blocks: (b,h,peighth of 8 p).  block = 128 threads = 4 warps.
// warp = p-pair of 2 (X broadcast); lanes = 32 n-slices of 4 n.
// Thread owns 2 p x 4 n state = 4 packed f32x2.  3-4 blocks/SM.
// Pipeline: NSTAGE=5 ring, 8-step tiles, ONE __syncthreads per tile,
// prefetch depth 3 tiles (wait_group <= 3).
#define NSTAGE 5
#define SSTEPS 8
#define NITER  (Lc / SSTEPS)   // 256

__global__ void __launch_bounds__(128, 4)
scan_kernel(const float* __restrict__ d_param,
            const float* __restrict__ init_state,
            float* __restrict__ out) {
    const int bid = blockIdx.x;
    const int b   = bid >> 8;
    const int h   = (bid >> 3) & 31;
    const int pc8 = bid & 7;
    const int tid = threadIdx.x;
    const int pg  = tid >> 5;      // warp id 0..3 -> p-pair (2 p)
    const int jn  = tid & 31;      // n-slice 0..31 (4 n each)
    const int bit0 = jn & 1;

    __shared__ __align__(16) float sB  [NSTAGE][SSTEPS][Nc];
    __shared__ __align__(16) float sC  [NSTAGE][SSTEPS][Nc];
    __shared__ __align__(16) float sX  [NSTAGE][SSTEPS][8];
    __shared__ __align__(16) float sG  [NSTAGE][SSTEPS][8];
    __shared__ __align__(16) float sdtA[NSTAGE][SSTEPS][2];

    const int q8 = (b * Hc + h) * 8 + pc8;
    const float4* gB   = (const float4*)(g_B + (size_t)b * Lc * Nc);   // 32 f4 / t
    const float4* gC   = (const float4*)(g_C + (size_t)b * Lc * Nc);
    const float4* gX   = (const float4*)(g_x + (size_t)q8 * Lc * 8);   // 2 f4 / t
    const float4* gG   = (const float4*)(g_g + (size_t)q8 * Lc * 8);
    const float4* gdtA = (const float4*)(g_dtA + (size_t)(b * Hc + h) * Lc * 2);

    // per stage: B/C = 256 float4 each, X/G = 16 float4 each, dtA = 4 float4
    auto issue_stage = [&](int k, int buf) {
        const float4* srcB = gB + (size_t)k * 256;
        const float4* srcC = gC + (size_t)k * 256;
        cpa16(&sB[buf][0][tid * 4], srcB + tid);
        cpa16(&sB[buf][0][(tid + 128) * 4], srcB + tid + 128);
        cpa16(&sC[buf][0][tid * 4], srcC + tid);
        cpa16(&sC[buf][0][(tid + 128) * 4], srcC + tid + 128);
        if (tid < 16) {
            cpa16(&sX[buf][0][tid * 4], gX + (size_t)k * 16 + tid);
        } else if (tid < 32) {
            cpa16(&sG[buf][0][(tid - 16) * 4], gG + (size_t)k * 16 + (tid - 16));
        } else if (tid < 36) {
            cpa16(&sdtA[buf][0][(tid - 32) * 4], gdtA + (size_t)k * 4 + (tid - 32));
        }
    };

    // init state; thread p = pc8*8 + pg*2 + pp, n = jn*4..jn*4+3
    uint64_t s2[2][2];
    #pragma unroll
    for (int pp = 0; pp < 2; ++pp) {
        int p = pc8 * 8 + pg * 2 + pp;
        const float4* ist = (const float4*)(init_state +
                            ((size_t)((b * Hc + h) * Pc + p)) * Nc + jn * 4);
        float4 v0 = ist[0];
        s2[pp][0] = pk2(v0.x, v0.y);
        s2[pp][1] = pk2(v0.z, v0.w);
    }
    const float Dh = d_param[h];

    // prologue: stages 0..3 into slots 0..3
    #pragma unroll
    for (int s = 0; s < NSTAGE - 1; ++s) {
        issue_stage(s, s);
        asm volatile("cp.async.commit_group;");
    }

    // writer lanes: jn < 2 write p = pc8*8 + pg*2 + jn
    float* outw = out + (size_t)b * Lc * DINNER + h * 64 + pc8 * 8 + pg * 2 + (jn & 1);

    int buf = 0;
    for (int k = 0; k < NITER; ++k) {
        asm volatile("cp.async.wait_group %0;" :: "n"(NSTAGE - 2));  // stage k landed
        __syncthreads();          // stage k visible to all; slot (k-1)%5 retired
        int kn = k + NSTAGE - 1;
        if (kn < NITER) {
            int nbuf = buf + NSTAGE - 1;
            if (nbuf >= NSTAGE) nbuf -= NSTAGE;     // == (k-1) % NSTAGE
            issue_stage(kn, nbuf);
        }
        asm volatile("cp.async.commit_group;");     // always commit (empty ok)

        float pY[SSTEPS][2];

        // ---- compute phase: pure FMA stream, partials to registers ----
        #pragma unroll
        for (int u = 0; u < SSTEPS; ++u) {
            float2 da = *(const float2*)&sdtA[buf][u][0];     // broadcast
            float2 xv = *(const float2*)&sX[buf][u][pg * 2];  // warp broadcast
            uint64_t dA2 = pk2(da.y, da.y);
            ulonglong2 bv = *(const ulonglong2*)&sB[buf][u][jn * 4];
            ulonglong2 cv = *(const ulonglong2*)&sC[buf][u][jn * 4];

            #pragma unroll
            for (int pp = 0; pp < 2; ++pp) {
                float xp = pp ? xv.y : xv.x;
                float dtx = da.x * xp;
                uint64_t dtx2 = pk2(dtx, dtx);
                s2[pp][0] = f2fma(dA2, s2[pp][0], f2mul(dtx2, bv.x));
                s2[pp][1] = f2fma(dA2, s2[pp][1], f2mul(dtx2, bv.y));
                uint64_t acc = f2mul(s2[pp][0], cv.x);
                acc = f2fma(s2[pp][1], cv.y, acc);
                float lo, hi; unpk2(acc, lo, hi);
                pY[u][pp] = lo + hi;
            }
        }

        // ---- reduction phase: 5 SHFL per step, 8-way ILP ----
        #pragma unroll
        for (int u = 0; u < SSTEPS; ++u) {
            // round 1 (off=1): select-exchange; lane ends holding pp == bit0
            float sA = bit0 ? pY[u][0] : pY[u][1];
            float rA = __shfl_xor_sync(0xffffffffu, sA, 1);
            float w = (bit0 ? pY[u][1] : pY[u][0]) + rA;
            // rounds 2..5: plain butterfly over remaining n-groups
            w += __shfl_xor_sync(0xffffffffu, w, 2);
            w += __shfl_xor_sync(0xffffffffu, w, 4);
            w += __shfl_xor_sync(0xffffffffu, w, 8);
            w += __shfl_xor_sync(0xffffffffu, w, 16);

            if (jn < 2) {
                float xw = sX[buf][u][pg * 2 + jn];
                float gv = sG[buf][u][pg * 2 + jn];
                int t = k * SSTEPS + u;
                outw[(size_t)t * DINNER] = (w + Dh * xw) * gv;
            }
        }

        if (++buf == NSTAGE) buf = 0;
    }
}

// ---------------- launch -----------------------------------------------------
extern "C" void kernel_launch(void* const* d_in, const int* in_sizes, int n_in,
                              void* d_out, int out_size) {
    const float* zxbcdt     = (const float*)d_in[0];
    const float* conv_w     = (const float*)d_in[1];
    const float* conv_b     = (const float*)d_in[2];
    const float* dt_bias    = (const float*)d_in[3];
    const float* a_log      = (const float*)d_in[4];
    const float* d_param    = (const float*)d_in[5];
    const float* dt_scale   = (const float*)d_in[6];
    const float* init_state = (const float*)d_in[7];
    float* out = (float*)d_out;

    dim3 pg(Bc * Lc, (DPROJ + 255) / 256);
    prepass_kernel<<<pg, 256>>>(zxbcdt, conv_w, conv_b, dt_bias, a_log, dt_scale);
    scan_kernel<<<Bc * Hc * 8, 128>>>(d_param, init_state, out);
}

// round 11
// speedup vs baseline: 1.3894x; 1.3894x over previous
#include <cuda_runtime.h>
#include <cstdint>

// Problem constants (fixed shapes for this problem instance)
#define Lc     2048
#define Bc     2
#define Hc     32
#define Pc     64
#define Nc     128
#define DPROJ  4384      // 2*d_inner + 2*dstate + nheads
#define DCONVC 2304      // d_inner + 2*dstate
#define DINNER 2048

// ---------------- scratch (static device globals; no runtime alloc) ---------
// x~ = dt*x duplicated pairs: [q4 = ((b*H+h)*4 + pquarter)][t][32]  (x,x per p)
__device__ __align__(16) float g_x [(size_t)Bc * Hc * 4 * Lc * 32];   // 67 MB
// (gate, Dh*x) pairs, same shape
__device__ __align__(16) float g_gd[(size_t)Bc * Hc * 4 * Lc * 32];   // 67 MB
__device__ __align__(16) float g_B [(size_t)Bc * Lc * Nc];            // 2 MB
__device__ __align__(16) float g_C [(size_t)Bc * Lc * Nc];            // 2 MB
// (dA,dA) duplicated pairs: [bh][t][2]
__device__ __align__(16) float g_dA[(size_t)Bc * Hc * Lc * 2];        // 1 MB

// ---------------- packed f32x2 helpers --------------------------------------
__device__ __forceinline__ uint64_t pk2(float lo, float hi) {
    uint64_t r;
    asm("mov.b64 %0, {%1,%2};" : "=l"(r) : "f"(lo), "f"(hi));
    return r;
}
__device__ __forceinline__ void unpk2(uint64_t v, float& lo, float& hi) {
    asm("mov.b64 {%0,%1}, %2;" : "=f"(lo), "=f"(hi) : "l"(v));
}
__device__ __forceinline__ uint64_t f2fma(uint64_t a, uint64_t b, uint64_t c) {
    uint64_t d;
    asm("fma.rn.f32x2 %0, %1, %2, %3;" : "=l"(d) : "l"(a), "l"(b), "l"(c));
    return d;
}
__device__ __forceinline__ uint64_t f2mul(uint64_t a, uint64_t b) {
    uint64_t d;
    asm("mul.rn.f32x2 %0, %1, %2;" : "=l"(d) : "l"(a), "l"(b));
    return d;
}
__device__ __forceinline__ void cpa16(void* sm, const void* gm) {
    unsigned sa = (unsigned)__cvta_generic_to_shared(sm);
    asm volatile("cp.async.cg.shared.global [%0], [%1], 16;" :: "r"(sa), "l"(gm));
}
__device__ __forceinline__ float fast_silu(float v) {
    return v * (1.f / (1.f + __expf(-v)));
}

// ---------------- pre-pass: conv + SiLU + dt/dA + operand packing -----------
// Work items: 2304 conv channels + 32 dt heads = 2336 per (b,t).
__global__ void prepass_kernel(const float* __restrict__ zx,
                               const float* __restrict__ cw,
                               const float* __restrict__ cb,
                               const float* __restrict__ dt_bias,
                               const float* __restrict__ a_log,
                               const float* __restrict__ d_param,
                               const float* __restrict__ dt_scale) {
    int bt  = blockIdx.x;            // b*L + t
    int b   = bt >> 11;
    int t   = bt & (Lc - 1);
    int idx = blockIdx.y * 256 + threadIdx.x;
    if (idx >= DCONVC + Hc) return;

    if (idx < DCONVC) {
        int cc = idx;                // conv channel; column in zx = DINNER + cc
        int col = DINNER + cc;
        float acc = cb[cc];
        const float* w = cw + cc * 4;
        #pragma unroll
        for (int i = 0; i < 4; ++i) {
            int l2 = t - 3 + i;
            if (l2 >= 0) acc += w[i] * zx[((size_t)(b * Lc + l2)) * DPROJ + col];
        }
        float v = fast_silu(acc);
        if (cc < DINNER) {
            int h = cc >> 6, p = cc & 63;
            // recompute dt for this head (cheap, avoids cross-thread dependency)
            float draw = zx[(size_t)bt * DPROJ + (DPROJ - Hc) + h] * dt_scale[h] + dt_bias[h];
            float dt = (draw > 20.f) ? draw : log1pf(expf(draw));
            dt = fminf(fmaxf(dt, 0.f), 100.f);
            float xt = dt * v;                       // x~ = dt * x
            size_t o = ((((size_t)(b * Hc + h) * 4 + (p >> 4)) * Lc + t) * 32 + (p & 15) * 2);
            g_x[o]     = xt;
            g_x[o + 1] = xt;
            float z = zx[(size_t)bt * DPROJ + cc];   // gate input (same channel idx)
            g_gd[o]     = fast_silu(z);              // gate
            g_gd[o + 1] = d_param[h] * v;            // Dh * x
        } else if (cc < DINNER + Nc) {
            g_B[((size_t)(b * Lc + t)) * Nc + (cc - DINNER)] = v;
        } else {
            g_C[((size_t)(b * Lc + t)) * Nc + (cc - DINNER - Nc)] = v;
        }
    } else {
        int h = idx - DCONVC;
        float draw = zx[(size_t)bt * DPROJ + (DPROJ - Hc) + h] * dt_scale[h] + dt_bias[h];
        float dt = (draw > 20.f) ? draw : log1pf(expf(draw));
        dt = fminf(fmaxf(dt, 0.f), 100.f);
        float A  = -expf(a_log[h]);
        float dA = expf(dt * A);
        size_t o = ((size_t)(b * Hc + h) * Lc + t) * 2;
        g_dA[o]     = dA;
        g_dA[o + 1] = dA;
    }
}

// ---------------- scan kernel -----------------------------------------------
// grid = 256 blocks: (b,h,pquarter of 16 p).  block = 128 threads = 4 warps.
// warp = p-group of 4 (X broadcast); lanes = 32 n-slices of 4 n.
// State update: s = dA*s + x~*B  (dt pre-folded, operands pre-packed).
// Pipeline: NSTAGE=4 ring, 8-step tiles, R5 schedule (2 barriers/tile).
#define NSTAGE 4
#define SSTEPS 8
#define NITER  (Lc / SSTEPS)   // 256

__global__ void __launch_bounds__(128, 2)
scan_kernel(const float* __restrict__ init_state,
            float* __restrict__ out) {
    const int bid = blockIdx.x;
    const int b   = bid >> 7;
    const int h   = (bid >> 2) & 31;
    const int pc4 = bid & 3;
    const int tid = threadIdx.x;
    const int pg  = tid >> 5;      // warp id 0..3 -> p-group (4 p)
    const int jn  = tid & 31;      // n-slice 0..31 (4 n each)
    const int bit0 = jn & 1;
    const int bit1 = (jn >> 1) & 1;

    __shared__ __align__(16) float sB [NSTAGE][SSTEPS][Nc];
    __shared__ __align__(16) float sC [NSTAGE][SSTEPS][Nc];
    __shared__ __align__(16) float sX [NSTAGE][SSTEPS][32];   // (x~,x~) pairs
    __shared__ __align__(16) float sGD[NSTAGE][SSTEPS][32];   // (g, Dh*x) pairs
    __shared__ __align__(16) float sdA[NSTAGE][SSTEPS][2];    // (dA,dA)

    const int q4 = (b * Hc + h) * 4 + pc4;
    const float4* gB  = (const float4*)(g_B + (size_t)b * Lc * Nc);   // 32 f4 / t
    const float4* gC  = (const float4*)(g_C + (size_t)b * Lc * Nc);
    const float4* gX  = (const float4*)(g_x  + (size_t)q4 * Lc * 32); // 8 f4 / t
    const float4* gGD = (const float4*)(g_gd + (size_t)q4 * Lc * 32);
    const float4* gdA = (const float4*)(g_dA + (size_t)(b * Hc + h) * Lc * 2);

    // per stage: B/C = 256 float4 each, X/GD = 64 float4 each, dA = 4 float4
    auto issue_stage = [&](int k, int buf) {
        const float4* srcB = gB + (size_t)k * 256;
        const float4* srcC = gC + (size_t)k * 256;
        cpa16(&sB[buf][0][tid * 4], srcB + tid);
        cpa16(&sB[buf][0][(tid + 128) * 4], srcB + tid + 128);
        cpa16(&sC[buf][0][tid * 4], srcC + tid);
        cpa16(&sC[buf][0][(tid + 128) * 4], srcC + tid + 128);
        if (tid < 64) {
            cpa16(&sX[buf][0][tid * 4], gX + (size_t)k * 64 + tid);
            if (tid < 4)
                cpa16(&sdA[buf][0][tid * 4], gdA + (size_t)k * 4 + tid);
        } else {
            cpa16(&sGD[buf][0][(tid - 64) * 4], gGD + (size_t)k * 64 + (tid - 64));
        }
    };

    // init state; thread p = pc4*16 + pg*4 + pp, n = jn*4..jn*4+3
    uint64_t s2[4][2];
    #pragma unroll
    for (int pp = 0; pp < 4; ++pp) {
        int p = pc4 * 16 + pg * 4 + pp;
        const float4* ist = (const float4*)(init_state +
                            ((size_t)((b * Hc + h) * Pc + p)) * Nc + jn * 4);
        float4 v0 = ist[0];
        s2[pp][0] = pk2(v0.x, v0.y);
        s2[pp][1] = pk2(v0.z, v0.w);
    }

    // prologue: fill the ring
    #pragma unroll
    for (int s = 0; s < NSTAGE; ++s) {
        issue_stage(s, s);
        asm volatile("cp.async.commit_group;");
    }

    // writer lanes: jn < 4 write p = pc4*16 + pg*4 + jn
    float* outw = out + (size_t)b * Lc * DINNER + h * 64 + pc4 * 16 + pg * 4 + (jn & 3);

    for (int k = 0; k < NITER; ++k) {
        asm volatile("cp.async.wait_group %0;" :: "n"(NSTAGE - 1));  // stage k landed
        __syncthreads();
        const int buf = k & (NSTAGE - 1);

        float pY[SSTEPS][4];

        // ---- compute phase: pure f32x2 FMA stream, zero packing movs ----
        #pragma unroll
        for (int u = 0; u < SSTEPS; ++u) {
            uint64_t dA2 = *(const uint64_t*)&sdA[buf][u][0];            // (dA,dA)
            ulonglong2 xa = *(const ulonglong2*)&sX[buf][u][pg * 8];     // (x0,x0),(x1,x1)
            ulonglong2 xb = *(const ulonglong2*)&sX[buf][u][pg * 8 + 4]; // (x2,x2),(x3,x3)
            ulonglong2 bv = *(const ulonglong2*)&sB[buf][u][jn * 4];
            ulonglong2 cv = *(const ulonglong2*)&sC[buf][u][jn * 4];

            #pragma unroll
            for (int pp = 0; pp < 4; ++pp) {
                uint64_t xx2 = (pp == 0) ? xa.x : (pp == 1) ? xa.y : (pp == 2) ? xb.x : xb.y;
                s2[pp][0] = f2fma(dA2, s2[pp][0], f2mul(xx2, bv.x));
                s2[pp][1] = f2fma(dA2, s2[pp][1], f2mul(xx2, bv.y));
                uint64_t acc = f2mul(s2[pp][0], cv.x);
                acc = f2fma(s2[pp][1], cv.y, acc);
                float lo, hi; unpk2(acc, lo, hi);
                pY[u][pp] = lo + hi;
            }
        }

        // ---- reduction phase: 6 SHFL per step, 8-way ILP ----
        #pragma unroll
        for (int u = 0; u < SSTEPS; ++u) {
            // round 1 (off=1): select-exchange, keep pp with (pp&1)==bit0
            float sA  = bit0 ? pY[u][0] : pY[u][1];
            float sBv = bit0 ? pY[u][2] : pY[u][3];
            float rA = __shfl_xor_sync(0xffffffffu, sA, 1);
            float rB = __shfl_xor_sync(0xffffffffu, sBv, 1);
            float u0 = (bit0 ? pY[u][1] : pY[u][0]) + rA;   // pp = bit0
            float u1 = (bit0 ? pY[u][3] : pY[u][2]) + rB;   // pp = 2 + bit0
            // round 2 (off=2): keep pp = bit0 + 2*bit1
            float sC2 = bit1 ? u0 : u1;
            float rC = __shfl_xor_sync(0xffffffffu, sC2, 2);
            float w = (bit1 ? u1 : u0) + rC;                // lane jn holds pp = jn&3
            // rounds 3..5: plain butterfly over remaining n-groups
            w += __shfl_xor_sync(0xffffffffu, w, 4);
            w += __shfl_xor_sync(0xffffffffu, w, 8);
            w += __shfl_xor_sync(0xffffffffu, w, 16);

            if (jn < 4) {
                float2 gd = *(const float2*)&sGD[buf][u][(pg * 4 + jn) * 2];
                int t = k * SSTEPS + u;
                outw[(size_t)t * DINNER] = (w + gd.y) * gd.x;
            }
        }

        __syncthreads();
        int kn = k + NSTAGE;
        if (kn < NITER) issue_stage(kn, buf);
        asm volatile("cp.async.commit_group;");
    }
}

// ---------------- launch -----------------------------------------------------
extern "C" void kernel_launch(void* const* d_in, const int* in_sizes, int n_in,
                              void* d_out, int out_size) {
    const float* zxbcdt     = (const float*)d_in[0];
    const float* conv_w     = (const float*)d_in[1];
    const float* conv_b     = (const float*)d_in[2];
    const float* dt_bias    = (const float*)d_in[3];
    const float* a_log      = (const float*)d_in[4];
    const float* d_param    = (const float*)d_in[5];
    const float* dt_scale   = (const float*)d_in[6];
    const float* init_state = (const float*)d_in[7];
    float* out = (float*)d_out;

    dim3 pg(Bc * Lc, (DCONVC + Hc + 255) / 256);
    prepass_kernel<<<pg, 256>>>(zxbcdt, conv_w, conv_b, dt_bias, a_log, d_param, dt_scale);
    scan_kernel<<<Bc * Hc * 4, 128>>>(init_state, out);
}